// round 2
// baseline (speedup 1.0000x reference)
#include <cuda_runtime.h>
#include <math.h>

#define LTOT 13326
#define LPAD 13344
#define NQ   4096
#define CK   288   // 32*9
#define CV   576   // 64*9

__constant__ int   c_off[5]   = {0, 4096, 7345, 9946, 11882};
__constant__ int   c_ws[5]    = {64, 57, 51, 44, 38};
__constant__ float c_ratio[5] = {63.0f/63.0f, 63.0f/56.0f, 63.0f/50.0f, 63.0f/43.0f, 63.0f/37.0f};

// scratch (device globals are the allowed scratch mechanism)
__device__ float g_mb  [2*32*4096];
__device__ float g_Q   [(size_t)2*NQ*CK];
__device__ float g_m   [(size_t)2*32*LTOT];
__device__ float g_base[(size_t)2*64*LTOT];
__device__ float g_K   [(size_t)2*LTOT*CK];
__device__ float g_V   [(size_t)2*LPAD*CV];
__device__ float g_S   [(size_t)2*NQ*LPAD];   // 437 MB scores / probs
__device__ float g_O   [(size_t)2*NQ*CV];
__device__ float g_invs[2*NQ];

// ---------------- helpers ----------------
__device__ __forceinline__ float cubw(float d) {
    d = fabsf(d);
    if (d <= 1.0f) return ((1.25f*d - 2.25f)*d)*d + 1.0f;           // A=-0.75
    if (d <  2.0f) return ((-0.75f*d + 3.75f)*d - 6.0f)*d + 3.0f;
    return 0.0f;
}

// exp(x) for x <= 0, poly on FFMA pipe (avoids MUFU bottleneck), rel err ~2e-6
__device__ __forceinline__ float fexp(float x) {
    float t = fmaxf(x * 1.4426950408889634f, -125.0f);
    int   ri = __float2int_rn(t);
    float f  = t - (float)ri;
    float z  = f * 0.6931471805599453f;
    float p  = 1.0f + z*(1.0f + z*(0.5f + z*(0.16666667f + z*(0.041666667f + z*0.0083333333f))));
    return __int_as_float((ri + 127) << 23) * p;
}

// ---------------- stage 0: match_base = prelu(Wb @ input + bb) ----------------
__global__ void k_matchbase(const float* __restrict__ inp, const float* __restrict__ Wb,
                            const float* __restrict__ bb, const float* __restrict__ ap) {
    int idx = blockIdx.x * blockDim.x + threadIdx.x;
    if (idx >= 2*32*4096) return;
    int pos = idx & 4095;
    int cm  = (idx >> 12) & 31;
    int b   = idx >> 17;
    const float* x = inp + ((size_t)b*64)*4096 + pos;
    const float* w = Wb + cm*64;
    float acc = bb[cm];
#pragma unroll
    for (int c = 0; c < 64; c++) acc = fmaf(w[c], x[(size_t)c*4096], acc);
    float a = ap[0];
    g_mb[idx] = acc >= 0.0f ? acc : a*acc;
}

// ---------------- stage 0b: Q patches [B,4096,288] ----------------
__global__ void k_buildQ() {
    int q = blockIdx.x, b = blockIdx.y;
    int y = q >> 6, x = q & 63;
    int t = threadIdx.x;            // 288
    int c = t / 9, r = t % 9;
    int dy = r/3 - 1, dx = r%3 - 1;
    int yy = y + dy, xx = x + dx;
    float v = 0.0f;
    if (yy >= 0 && yy < 64 && xx >= 0 && xx < 64)
        v = g_mb[((size_t)b*32 + c)*4096 + yy*64 + xx];
    g_Q[((size_t)b*NQ + q)*CK + t] = v;
}

// ---------------- stage 1: bicubic resize + conv_match/conv_assembly ----------------
__global__ __launch_bounds__(128) void k_resize_conv(const float* __restrict__ ref,
        const float* __restrict__ Wm, const float* __restrict__ bm,
        const float* __restrict__ Wa, const float* __restrict__ ba,
        const float* __restrict__ ap) {
    __shared__ float Wsh[96][65];     // rows 0..31 = Wm, 32..95 = Wa
    __shared__ float bsh[96];
    __shared__ float rv[8][65];       // resized pixel vectors for 8 positions
    int b = blockIdx.y;
    int t = threadIdx.x;
    for (int i = t; i < 96*64; i += 128) {
        int o = i >> 6, c = i & 63;
        Wsh[o][c] = (o < 32) ? Wm[o*64 + c] : Wa[(o-32)*64 + c];
    }
    if (t < 96) bsh[t] = (t < 32) ? bm[t] : ba[t-32];
    float a = ap[0];
    int p0 = blockIdx.x * 8;

    // resize: 512 tasks, mapped (c = i>>3, pi = i&7) for coalesced tap loads
    for (int i = t; i < 512; i += 128) {
        int c = i >> 3, pi = i & 7;
        int pos = p0 + pi;
        float val = 0.0f;
        if (pos < LTOT) {
            int s = 0;
            while (s < 4 && pos >= c_off[s+1]) s++;
            int lp = pos - c_off[s];
            int ws = c_ws[s];
            int y = lp / ws, x = lp - y*ws;
            float ratio = c_ratio[s];
            float ry = (float)y * ratio, rx = (float)x * ratio;
            int iy0 = (int)floorf(ry); float fy = ry - (float)iy0;
            int ix0 = (int)floorf(rx); float fx = rx - (float)ix0;
            float wy0=cubw(fy+1.0f), wy1=cubw(fy), wy2=cubw(1.0f-fy), wy3=cubw(2.0f-fy);
            float wx0=cubw(fx+1.0f), wx1=cubw(fx), wx2=cubw(1.0f-fx), wx3=cubw(2.0f-fx);
            float wyv[4] = {wy0,wy1,wy2,wy3};
            float wxv[4] = {wx0,wx1,wx2,wx3};
            const float* ch = ref + ((size_t)b*64 + c)*4096;
#pragma unroll
            for (int u = 0; u < 4; u++) {
                int yy = min(max(iy0 - 1 + u, 0), 63);
                const float* rowp = ch + yy*64;
                float racc = 0.0f;
#pragma unroll
                for (int v = 0; v < 4; v++) {
                    int xx = min(max(ix0 - 1 + v, 0), 63);
                    racc = fmaf(wxv[v], rowp[xx], racc);
                }
                val = fmaf(wyv[u], racc, val);
            }
        }
        rv[pi][c] = val;
    }
    __syncthreads();

    // conv: 768 tasks (8 pos x 96 out channels)
    for (int i = t; i < 768; i += 128) {
        int pi = i / 96, o = i % 96;
        int pos = p0 + pi;
        if (pos >= LTOT) continue;
        float acc = bsh[o];
#pragma unroll
        for (int c = 0; c < 64; c++) acc = fmaf(Wsh[o][c], rv[pi][c], acc);
        acc = acc >= 0.0f ? acc : a*acc;
        if (o < 32) g_m   [((size_t)b*32 + o)     *LTOT + pos] = acc;
        else        g_base[((size_t)b*64 + (o-32))*LTOT + pos] = acc;
    }
}

// ---------------- stage 2: build normalized K [B,L,288] and V [B,LPAD,576] ----------------
__global__ __launch_bounds__(288) void k_buildKV() {
    int l = blockIdx.x, b = blockIdx.y;
    int t = threadIdx.x;    // 288 = 9 warps
    if (l >= LTOT) {        // zero V pad rows (uniform branch per block)
        for (int i = t; i < CV; i += 288)
            g_V[((size_t)b*LPAD + l)*CV + i] = 0.0f;
        return;
    }
    int s = 0;
    while (s < 4 && l >= c_off[s+1]) s++;
    int ws = c_ws[s];
    int lp = l - c_off[s];
    int y = lp / ws, x = lp - y*ws;

    int c = t / 9, r = t % 9;
    int dy = r/3 - 1, dx = r%3 - 1;
    int yy = y + dy, xx = x + dx;
    float kv = 0.0f;
    if (yy >= 0 && yy < ws && xx >= 0 && xx < ws)
        kv = g_m[((size_t)b*32 + c)*LTOT + c_off[s] + yy*ws + xx];

    // norm over 288
    float v2 = kv*kv;
#pragma unroll
    for (int o = 16; o > 0; o >>= 1) v2 += __shfl_down_sync(0xffffffffu, v2, o);
    __shared__ float red[9];
    __shared__ float nrm_sh;
    if ((t & 31) == 0) red[t >> 5] = v2;
    __syncthreads();
    if (t == 0) {
        float tot = 0.0f;
#pragma unroll
        for (int i = 0; i < 9; i++) tot += red[i];
        nrm_sh = fmaxf(sqrtf(tot), 1e-4f);
    }
    __syncthreads();
    float inv = 1.0f / nrm_sh;
    g_K[((size_t)b*LTOT + l)*CK + t] = kv * inv;

    // V (2 elements per thread)
    for (int i = t; i < CV; i += 288) {
        int c2 = i / 9, r2 = i % 9;
        int dy2 = r2/3 - 1, dx2 = r2%3 - 1;
        int yy2 = y + dy2, xx2 = x + dx2;
        float v = 0.0f;
        if (yy2 >= 0 && yy2 < ws && xx2 >= 0 && xx2 < ws)
            v = g_base[((size_t)b*64 + c2)*LTOT + c_off[s] + yy2*ws + xx2];
        g_V[((size_t)b*LPAD + l)*CV + i] = v;
    }
}

// ---------------- stage 3: S = Q * K^T  (M=4096, N=13326, K=288) ----------------
__global__ __launch_bounds__(256) void k_gemm_qk() {
    const int b = blockIdx.z;
    const float* Q  = g_Q + (size_t)b*NQ*CK;
    const float* Kn = g_K + (size_t)b*LTOT*CK;
    float* S = g_S + (size_t)b*NQ*LPAD;
    __shared__ float As[8][128];
    __shared__ float Bs[8][128];
    const int bm = blockIdx.y << 7;
    const int bn = blockIdx.x << 7;
    const int t  = threadIdx.x;
    const int lr = t >> 1;
    const int lk = (t & 1) << 2;
    const int ty = t >> 4;
    const int tx = t & 15;
    float acc[8][8];
#pragma unroll
    for (int i = 0; i < 8; i++)
#pragma unroll
        for (int j = 0; j < 8; j++) acc[i][j] = 0.0f;

    const int gn = bn + lr;
    const float* Abase = Q + (size_t)(bm + lr)*CK + lk;
    const float* Bbase = (gn < LTOT) ? (Kn + (size_t)gn*CK + lk) : 0;

    for (int k0 = 0; k0 < CK; k0 += 8) {
        float4 a4 = *(const float4*)(Abase + k0);
        float4 b4 = make_float4(0.f, 0.f, 0.f, 0.f);
        if (Bbase) b4 = *(const float4*)(Bbase + k0);
        As[lk+0][lr] = a4.x; As[lk+1][lr] = a4.y; As[lk+2][lr] = a4.z; As[lk+3][lr] = a4.w;
        Bs[lk+0][lr] = b4.x; Bs[lk+1][lr] = b4.y; Bs[lk+2][lr] = b4.z; Bs[lk+3][lr] = b4.w;
        __syncthreads();
#pragma unroll
        for (int kk = 0; kk < 8; kk++) {
            float4 a0 = *(const float4*)&As[kk][ty << 3];
            float4 a1 = *(const float4*)&As[kk][(ty << 3) + 4];
            float4 b0 = *(const float4*)&Bs[kk][tx << 3];
            float4 b1 = *(const float4*)&Bs[kk][(tx << 3) + 4];
            float ra[8] = {a0.x,a0.y,a0.z,a0.w,a1.x,a1.y,a1.z,a1.w};
            float rb[8] = {b0.x,b0.y,b0.z,b0.w,b1.x,b1.y,b1.z,b1.w};
#pragma unroll
            for (int i = 0; i < 8; i++)
#pragma unroll
                for (int j = 0; j < 8; j++)
                    acc[i][j] = fmaf(ra[i], rb[j], acc[i][j]);
        }
        __syncthreads();
    }
#pragma unroll
    for (int i = 0; i < 8; i++) {
        int gq = bm + (ty << 3) + i;
        float* srow = S + (size_t)gq*LPAD;
#pragma unroll
        for (int j = 0; j < 8; j++) {
            int gl = bn + (tx << 3) + j;
            if (gl < LTOT) srow[gl] = acc[i][j];
        }
    }
}

// ---------------- stage 4: softmax (in-place exp, unnormalized; invsum saved) ----------------
__global__ __launch_bounds__(256) void k_softmax() {
    int q = blockIdx.x, b = blockIdx.y;
    float* row = g_S + ((size_t)b*NQ + q)*LPAD;
    int t = threadIdx.x;
    __shared__ float red[8];
    __shared__ float bc;

    float m = -1e30f;
    for (int l = t; l < LTOT; l += 256) m = fmaxf(m, row[l]);
#pragma unroll
    for (int o = 16; o > 0; o >>= 1) m = fmaxf(m, __shfl_down_sync(0xffffffffu, m, o));
    if ((t & 31) == 0) red[t >> 5] = m;
    __syncthreads();
    if (t == 0) {
        float mm = red[0];
#pragma unroll
        for (int i = 1; i < 8; i++) mm = fmaxf(mm, red[i]);
        bc = mm;
    }
    __syncthreads();
    m = bc;

    float s = 0.0f;
    for (int l = t; l < LTOT; l += 256) {
        float e = fexp((row[l] - m) * 10.0f);
        row[l] = e;
        s += e;
    }
    if (t < (LPAD - LTOT)) row[LTOT + t] = 0.0f;   // zero pad cols for GEMM2
#pragma unroll
    for (int o = 16; o > 0; o >>= 1) s += __shfl_down_sync(0xffffffffu, s, o);
    if ((t & 31) == 0) red[t >> 5] = s;
    __syncthreads();
    if (t == 0) {
        float tot = 0.0f;
#pragma unroll
        for (int i = 0; i < 8; i++) tot += red[i];
        g_invs[b*NQ + q] = 1.0f / tot;
    }
}

// ---------------- stage 5: O = P * V  (M=4096, N=576, K=13344) ----------------
__global__ __launch_bounds__(256) void k_gemm_pv() {
    const int b = blockIdx.z;
    const float* P = g_S + (size_t)b*NQ*LPAD;
    const float* V = g_V + (size_t)b*LPAD*CV;
    float* O = g_O + (size_t)b*NQ*CV;
    const float* is = g_invs + b*NQ;
    __shared__ float As[8][128];
    __shared__ float Bs[8][64];
    const int bm = blockIdx.y << 7;
    const int bn = blockIdx.x << 6;
    const int t  = threadIdx.x;
    const int lr = t >> 1;
    const int lk = (t & 1) << 2;
    const int ty = t >> 4;      // 0..15 -> 8 rows each
    const int tx = t & 15;      // 0..15 -> 4 cols each
    float acc[8][4];
#pragma unroll
    for (int i = 0; i < 8; i++)
#pragma unroll
        for (int j = 0; j < 4; j++) acc[i][j] = 0.0f;

    const float* Abase = P + (size_t)(bm + lr)*LPAD + lk;
    const int bkr = t >> 4;          // for t<128: k-row 0..7
    const int bnc = (t & 15) << 2;   // col*4

    for (int k0 = 0; k0 < LPAD; k0 += 8) {
        float4 a4 = *(const float4*)(Abase + k0);
        As[lk+0][lr] = a4.x; As[lk+1][lr] = a4.y; As[lk+2][lr] = a4.z; As[lk+3][lr] = a4.w;
        if (t < 128) {
            float4 b4 = *(const float4*)(V + (size_t)(k0 + bkr)*CV + bn + bnc);
            Bs[bkr][bnc+0] = b4.x; Bs[bkr][bnc+1] = b4.y; Bs[bkr][bnc+2] = b4.z; Bs[bkr][bnc+3] = b4.w;
        }
        __syncthreads();
#pragma unroll
        for (int kk = 0; kk < 8; kk++) {
            float4 a0 = *(const float4*)&As[kk][ty << 3];
            float4 a1 = *(const float4*)&As[kk][(ty << 3) + 4];
            float4 b0 = *(const float4*)&Bs[kk][tx << 2];
            float ra[8] = {a0.x,a0.y,a0.z,a0.w,a1.x,a1.y,a1.z,a1.w};
            float rb[4] = {b0.x,b0.y,b0.z,b0.w};
#pragma unroll
            for (int i = 0; i < 8; i++)
#pragma unroll
                for (int j = 0; j < 4; j++)
                    acc[i][j] = fmaf(ra[i], rb[j], acc[i][j]);
        }
        __syncthreads();
    }
#pragma unroll
    for (int i = 0; i < 8; i++) {
        int gq = bm + (ty << 3) + i;
        float w = is[gq];
        float4 o4 = make_float4(acc[i][0]*w, acc[i][1]*w, acc[i][2]*w, acc[i][3]*w);
        *(float4*)(O + (size_t)gq*CV + bn + (tx << 2)) = o4;
    }
}

// ---------------- stage 6: transposed-conv gather + residual ----------------
__global__ void k_final(const float* __restrict__ inp, float* __restrict__ out) {
    int idx = blockIdx.x * blockDim.x + threadIdx.x;   // 2*64*64*64
    if (idx >= 2*64*64*64) return;
    int j = idx & 63;
    int i = (idx >> 6) & 63;
    int c = (idx >> 12) & 63;
    int b = idx >> 18;
    float acc = 0.0f;
#pragma unroll
    for (int a = 0; a < 3; a++) {
        int qi = i + 1 - a;
        if (qi < 0 || qi >= 64) continue;
#pragma unroll
        for (int d = 0; d < 3; d++) {
            int qj = j + 1 - d;
            if (qj < 0 || qj >= 64) continue;
            acc += g_O[((size_t)b*NQ + qi*64 + qj)*CV + c*9 + a*3 + d];
        }
    }
    out[idx] = inp[idx] + 0.25f * acc;
}

// ---------------- launch ----------------
extern "C" void kernel_launch(void* const* d_in, const int* in_sizes, int n_in,
                              void* d_out, int out_size) {
    const float* input     = (const float*)d_in[0];
    const float* input_ref = (const float*)d_in[1];
    const float* Wb = (const float*)d_in[2];
    const float* bb = (const float*)d_in[3];
    const float* Wm = (const float*)d_in[4];
    const float* bm = (const float*)d_in[5];
    const float* Wa = (const float*)d_in[6];
    const float* ba = (const float*)d_in[7];
    const float* ap = (const float*)d_in[8];
    float* out = (float*)d_out;

    k_matchbase  <<<1024, 256>>>(input, Wb, bb, ap);
    k_buildQ     <<<dim3(4096, 2), 288>>>();
    k_resize_conv<<<dim3(1666, 2), 128>>>(input_ref, Wm, bm, Wa, ba, ap);
    k_buildKV    <<<dim3(LPAD, 2), 288>>>();
    k_gemm_qk    <<<dim3(105, 32, 2), 256>>>();
    k_softmax    <<<dim3(4096, 2), 256>>>();
    k_gemm_pv    <<<dim3(9, 32, 2), 256>>>();
    k_final      <<<2048, 256>>>(input, out);
}

// round 3
// speedup vs baseline: 2.7391x; 2.7391x over previous
#include <cuda_runtime.h>
#include <math.h>

#define LTOT 13326
#define LPAD 13440     // 105*128, padded
#define NQ   4096
#define GUARD 4096

__constant__ int   c_off[5]   = {0, 4096, 7345, 9946, 11882};
__constant__ int   c_ws[5]    = {64, 57, 51, 44, 38};
__constant__ float c_ratio[5] = {1.0f, 63.0f/56.0f, 63.0f/50.0f, 63.0f/43.0f, 63.0f/37.0f};

__device__ __align__(16) float g_mb  [2*32*NQ];
__device__ __align__(16) float g_m   [(size_t)2*32*LPAD];
__device__ __align__(16) float g_base[(size_t)2*64*LPAD];
__device__ __align__(16) float g_sq  [2*LPAD];
__device__ __align__(16) float g_invn[2*LPAD];
__device__ __align__(16) unsigned g_meta[LPAD];
__device__ __align__(16) float g_G   [(size_t)2*NQ*LPAD + 2*GUARD]; // G, then W
__device__ __align__(16) float g_P   [(size_t)2*NQ*LPAD + 2*GUARD]; // softmax probs
__device__ __align__(16) float g_part[(size_t)8*2*64*NQ];

// ---------------- helpers ----------------
__device__ __forceinline__ float cubw(float d) {
    d = fabsf(d);
    if (d <= 1.0f) return ((1.25f*d - 2.25f)*d)*d + 1.0f;
    if (d <  2.0f) return ((-0.75f*d + 3.75f)*d - 6.0f)*d + 3.0f;
    return 0.0f;
}

__device__ __forceinline__ float fexp(float x) {
    float t = fmaxf(x * 1.4426950408889634f, -125.0f);
    int   ri = __float2int_rn(t);
    float f  = t - (float)ri;
    float z  = f * 0.6931471805599453f;
    float p  = 1.0f + z*(1.0f + z*(0.5f + z*(0.16666667f + z*(0.041666667f + z*0.0083333333f))));
    return __int_as_float((ri + 127) << 23) * p;
}

// load 4-float window at arbitrary (possibly negative) offset o of a row
__device__ __forceinline__ void ldwin4(const float* p, int o, float w[4]) {
    const float* ap = p + (o & ~3);
    int d = o & 3;
    float4 lo = *(const float4*)ap;
    if (d == 0) { w[0]=lo.x; w[1]=lo.y; w[2]=lo.z; w[3]=lo.w; return; }
    float4 hi = *(const float4*)(ap + 4);
    if (d == 1)      { w[0]=lo.y; w[1]=lo.z; w[2]=lo.w; w[3]=hi.x; }
    else if (d == 2) { w[0]=lo.z; w[1]=lo.w; w[2]=hi.x; w[3]=hi.y; }
    else             { w[0]=lo.w; w[1]=hi.x; w[2]=hi.y; w[3]=hi.z; }
}

// ---------------- stage 0: match_base ----------------
__global__ void k_matchbase(const float* __restrict__ inp, const float* __restrict__ Wb,
                            const float* __restrict__ bb, const float* __restrict__ ap) {
    int idx = blockIdx.x * blockDim.x + threadIdx.x;
    if (idx >= 2*32*4096) return;
    int pos = idx & 4095;
    int cm  = (idx >> 12) & 31;
    int b   = idx >> 17;
    const float* x = inp + ((size_t)b*64)*4096 + pos;
    const float* w = Wb + cm*64;
    float acc = bb[cm];
#pragma unroll
    for (int c = 0; c < 64; c++) acc = fmaf(w[c], x[(size_t)c*4096], acc);
    float a = ap[0];
    g_mb[idx] = acc >= 0.0f ? acc : a*acc;
}

// ---------------- stage 1: resize + conv_match/assembly ----------------
__global__ __launch_bounds__(128) void k_resize_conv(const float* __restrict__ ref,
        const float* __restrict__ Wm, const float* __restrict__ bmv,
        const float* __restrict__ Wa, const float* __restrict__ ba,
        const float* __restrict__ ap) {
    __shared__ float Wsh[96][65];
    __shared__ float bsh[96];
    __shared__ float rv[8][65];
    int b = blockIdx.y;
    int t = threadIdx.x;
    for (int i = t; i < 96*64; i += 128) {
        int o = i >> 6, c = i & 63;
        Wsh[o][c] = (o < 32) ? Wm[o*64 + c] : Wa[(o-32)*64 + c];
    }
    if (t < 96) bsh[t] = (t < 32) ? bmv[t] : ba[t-32];
    float a = ap[0];
    int p0 = blockIdx.x * 8;

    for (int i = t; i < 512; i += 128) {
        int c = i >> 3, pi = i & 7;
        int pos = p0 + pi;
        float val = 0.0f;
        if (pos < LTOT) {
            int s = 0;
            while (s < 4 && pos >= c_off[s+1]) s++;
            int lp = pos - c_off[s];
            int ws = c_ws[s];
            int y = lp / ws, x = lp - y*ws;
            float ratio = c_ratio[s];
            float ry = (float)y * ratio, rx = (float)x * ratio;
            int iy0 = (int)floorf(ry); float fy = ry - (float)iy0;
            int ix0 = (int)floorf(rx); float fx = rx - (float)ix0;
            float wyv[4] = {cubw(fy+1.0f), cubw(fy), cubw(1.0f-fy), cubw(2.0f-fy)};
            float wxv[4] = {cubw(fx+1.0f), cubw(fx), cubw(1.0f-fx), cubw(2.0f-fx)};
            const float* ch = ref + ((size_t)b*64 + c)*4096;
#pragma unroll
            for (int u = 0; u < 4; u++) {
                int yy = min(max(iy0 - 1 + u, 0), 63);
                const float* rowp = ch + yy*64;
                float racc = 0.0f;
#pragma unroll
                for (int v = 0; v < 4; v++) {
                    int xx = min(max(ix0 - 1 + v, 0), 63);
                    racc = fmaf(wxv[v], rowp[xx], racc);
                }
                val = fmaf(wyv[u], racc, val);
            }
        }
        rv[pi][c] = val;
    }
    __syncthreads();

    for (int i = t; i < 768; i += 128) {
        int pi = i / 96, o = i % 96;
        int pos = p0 + pi;
        if (pos >= LTOT) continue;
        float acc = bsh[o];
#pragma unroll
        for (int c = 0; c < 64; c++) acc = fmaf(Wsh[o][c], rv[pi][c], acc);
        acc = acc >= 0.0f ? acc : a*acc;
        if (o < 32) g_m   [((size_t)b*32 + o)     *LPAD + pos] = acc;
        else        g_base[((size_t)b*64 + (o-32))*LPAD + pos] = acc;
    }
}

// ---------------- stage 2a: meta, sq, pad zeroing ----------------
__global__ void k_prep() {
    int l = blockIdx.x*128 + threadIdx.x;
    if (l >= LPAD) return;
    if (l >= LTOT) {
        g_meta[l] = 1u;   // ws=1, mask=0
        for (int r = 0; r < 64;  r++) g_m   [(size_t)r*LPAD + l] = 0.0f;
        for (int r = 0; r < 128; r++) g_base[(size_t)r*LPAD + l] = 0.0f;
        g_sq[l] = 0.0f; g_sq[LPAD + l] = 0.0f;
        return;
    }
    int s = 0;
    while (s < 4 && l >= c_off[s+1]) s++;
    int ws = c_ws[s], lp = l - c_off[s];
    int ly = lp / ws, lx = lp - ly*ws;
    unsigned mask = 0;
#pragma unroll
    for (int dy = -1; dy <= 1; dy++)
#pragma unroll
        for (int dx = -1; dx <= 1; dx++) {
            int yy = ly+dy, xx = lx+dx;
            if (yy >= 0 && yy < ws && xx >= 0 && xx < ws)
                mask |= 1u << ((dy+1)*3 + (dx+1));
        }
    g_meta[l] = (unsigned)ws | (mask << 8);
#pragma unroll
    for (int b = 0; b < 2; b++) {
        float a = 0.0f;
        for (int c = 0; c < 32; c++) {
            float v = g_m[((size_t)b*32 + c)*LPAD + l];
            a = fmaf(v, v, a);
        }
        g_sq[b*LPAD + l] = a;
    }
}

// ---------------- stage 2b: invn = 10 / max(sqrt(9-tap sq), 1e-4) ----------------
__global__ void k_invnrm() {
    int l = blockIdx.x*128 + threadIdx.x;
    int b = blockIdx.y;
    if (l >= LPAD) return;
    if (l >= LTOT) { g_invn[b*LPAD + l] = 0.0f; return; }
    unsigned mt = g_meta[l];
    int ws = (int)(mt & 255u);
    float a = 0.0f;
#pragma unroll
    for (int dy = -1; dy <= 1; dy++)
#pragma unroll
        for (int dx = -1; dx <= 1; dx++) {
            int bi = (dy+1)*3 + (dx+1);
            if ((mt >> (8 + bi)) & 1u) a += g_sq[b*LPAD + l + dy*ws + dx];
        }
    g_invn[b*LPAD + l] = 10.0f / fmaxf(sqrtf(a), 1e-4f);
}

// ---------------- stage 3: G = mb^T * m  (M=4096, N=13440, K=32) ----------------
__global__ __launch_bounds__(256) void k_gemm_G() {
    const int b  = blockIdx.z;
    const int bm = blockIdx.y << 7;
    const int bn = blockIdx.x << 7;
    const float* A  = g_mb + (size_t)b*32*NQ;
    const float* Bm = g_m  + (size_t)b*32*LPAD;
    float* G = g_G + GUARD + (size_t)b*NQ*LPAD;
    __shared__ float As[32][128];
    __shared__ float Bs[32][128];
    const int t = threadIdx.x;
#pragma unroll
    for (int j = 0; j < 4; j++) {
        int id = t + j*256;
        int row = id >> 5, c4 = (id & 31) << 2;
        *(float4*)&As[row][c4] = *(const float4*)(A  + (size_t)row*NQ   + bm + c4);
        *(float4*)&Bs[row][c4] = *(const float4*)(Bm + (size_t)row*LPAD + bn + c4);
    }
    __syncthreads();
    const int ty = t >> 4, tx = t & 15;
    float acc[8][8] = {};
#pragma unroll
    for (int kk = 0; kk < 32; kk++) {
        float4 a0 = *(const float4*)&As[kk][ty << 3];
        float4 a1 = *(const float4*)&As[kk][(ty << 3) + 4];
        float4 b0 = *(const float4*)&Bs[kk][tx << 3];
        float4 b1 = *(const float4*)&Bs[kk][(tx << 3) + 4];
        float ra[8] = {a0.x,a0.y,a0.z,a0.w,a1.x,a1.y,a1.z,a1.w};
        float rb[8] = {b0.x,b0.y,b0.z,b0.w,b1.x,b1.y,b1.z,b1.w};
#pragma unroll
        for (int i = 0; i < 8; i++)
#pragma unroll
            for (int j = 0; j < 8; j++)
                acc[i][j] = fmaf(ra[i], rb[j], acc[i][j]);
    }
#pragma unroll
    for (int i = 0; i < 8; i++) {
        float* row = G + (size_t)(bm + (ty << 3) + i)*LPAD + bn + (tx << 3);
        *(float4*)row     = make_float4(acc[i][0],acc[i][1],acc[i][2],acc[i][3]);
        *(float4*)(row+4) = make_float4(acc[i][4],acc[i][5],acc[i][6],acc[i][7]);
    }
}

// ---------------- stages 4/5: 9-tap shift (+softmax for SM variant) ----------------
template<bool SM>
__global__ __launch_bounds__(256) void k_shift() {
    const int q = blockIdx.x, b = blockIdx.y;
    const int y = q >> 6, x = q & 63;
    unsigned qmask = 0;
#pragma unroll
    for (int dy = -1; dy <= 1; dy++)
#pragma unroll
        for (int dx = -1; dx <= 1; dx++) {
            int yy = y+dy, xx = x+dx;
            if (yy >= 0 && yy < 64 && xx >= 0 && xx < 64)
                qmask |= 1u << ((dy+1)*3 + (dx+1));
        }
    const float* srcbase = (SM ? g_G : g_P) + GUARD + (size_t)b*NQ*LPAD;
    float* dst = (SM ? g_P : g_G) + GUARD + ((size_t)b*NQ + q)*LPAD;
    const float* R[9];
#pragma unroll
    for (int dy = -1; dy <= 1; dy++)
#pragma unroll
        for (int dx = -1; dx <= 1; dx++)
            R[(dy+1)*3 + (dx+1)] = srcbase + (size_t)(q + dy*64 + dx)*LPAD;

    const int t = threadIdx.x;
    extern __shared__ float srow[];
    __shared__ float red[8];
    __shared__ float bcast;
    float lmax = -1e30f;

    for (int g = t; g < LPAD/4; g += 256) {
        int l4 = g << 2;
        uint4 mt = *(const uint4*)(g_meta + l4);
        unsigned m0 = (mt.x>>8)&qmask, m1 = (mt.y>>8)&qmask,
                 m2 = (mt.z>>8)&qmask, m3 = (mt.w>>8)&qmask;
        unsigned anym = m0|m1|m2|m3;
        float acc[4] = {0.f,0.f,0.f,0.f};
        if (anym) {
            int ws0 = (int)(mt.x & 255u), ws3 = (int)(mt.w & 255u);
            if (ws0 == ws3) {
#pragma unroll
                for (int dy = -1; dy <= 1; dy++)
#pragma unroll
                    for (int dx = -1; dx <= 1; dx++) {
                        const int bi = (dy+1)*3 + (dx+1);
                        if (!((anym >> bi) & 1u)) continue;
                        float w[4];
                        ldwin4(R[bi], l4 + dy*ws0 + dx, w);
                        if ((m0>>bi)&1u) acc[0] += w[0];
                        if ((m1>>bi)&1u) acc[1] += w[1];
                        if ((m2>>bi)&1u) acc[2] += w[2];
                        if ((m3>>bi)&1u) acc[3] += w[3];
                    }
            } else {
                unsigned mm[4] = {m0,m1,m2,m3};
                int wss[4] = {(int)(mt.x&255u),(int)(mt.y&255u),(int)(mt.z&255u),(int)(mt.w&255u)};
#pragma unroll
                for (int e = 0; e < 4; e++) {
#pragma unroll
                    for (int dy = -1; dy <= 1; dy++)
#pragma unroll
                        for (int dx = -1; dx <= 1; dx++) {
                            int bi = (dy+1)*3 + (dx+1);
                            if ((mm[e] >> bi) & 1u) acc[e] += R[bi][l4+e + dy*wss[e] + dx];
                        }
                }
            }
        }
        if (SM) {
            float4 iv = *(const float4*)(g_invn + b*LPAD + l4);
            float s0 = (l4+0 < LTOT) ? acc[0]*iv.x : -1e30f;
            float s1 = (l4+1 < LTOT) ? acc[1]*iv.y : -1e30f;
            float s2 = (l4+2 < LTOT) ? acc[2]*iv.z : -1e30f;
            float s3 = (l4+3 < LTOT) ? acc[3]*iv.w : -1e30f;
            *(float4*)(srow + l4) = make_float4(s0,s1,s2,s3);
            lmax = fmaxf(lmax, fmaxf(fmaxf(s0,s1), fmaxf(s2,s3)));
        } else {
            *(float4*)(dst + l4) = make_float4(acc[0],acc[1],acc[2],acc[3]);
        }
    }
    if (SM) {
#pragma unroll
        for (int o = 16; o > 0; o >>= 1) lmax = fmaxf(lmax, __shfl_xor_sync(0xffffffffu, lmax, o));
        if ((t & 31) == 0) red[t >> 5] = lmax;
        __syncthreads();
        if (t == 0) {
            float m = red[0];
#pragma unroll
            for (int i = 1; i < 8; i++) m = fmaxf(m, red[i]);
            bcast = m;
        }
        __syncthreads();
        float M = bcast;
        float lsum = 0.0f;
        for (int g = t; g < LPAD/4; g += 256) {
            int l4 = g << 2;
            float4 v = *(float4*)(srow + l4);
            float4 e = make_float4(fexp(v.x-M), fexp(v.y-M), fexp(v.z-M), fexp(v.w-M));
            *(float4*)(srow + l4) = e;
            lsum += (e.x + e.y) + (e.z + e.w);
        }
#pragma unroll
        for (int o = 16; o > 0; o >>= 1) lsum += __shfl_xor_sync(0xffffffffu, lsum, o);
        __syncthreads();
        if ((t & 31) == 0) red[t >> 5] = lsum;
        __syncthreads();
        if (t == 0) {
            float s = 0.0f;
#pragma unroll
            for (int i = 0; i < 8; i++) s += red[i];
            bcast = 1.0f / s;
        }
        __syncthreads();
        float inv = bcast;
        for (int g = t; g < LPAD/4; g += 256) {
            int l4 = g << 2;
            float4 e = *(float4*)(srow + l4);
            *(float4*)(dst + l4) = make_float4(e.x*inv, e.y*inv, e.z*inv, e.w*inv);
        }
    }
}

// ---------------- stage 6: out_part = W * base^T (split-K=8) ----------------
__global__ __launch_bounds__(256) void k_gemm_W() {
    const int split = blockIdx.x;          // 0..7
    const int bm = blockIdx.y << 7;        // 32 blocks
    const int b  = blockIdx.z;
    const float* W  = g_G + GUARD + (size_t)b*NQ*LPAD;
    const float* Bb = g_base + (size_t)b*64*LPAD;
    __shared__ float As[8][128];
    __shared__ float Bs[8][64];
    const int t = threadIdx.x;
    const int ty = t >> 4, tx = t & 15;
    float acc[8][4] = {};
    const int kbeg = split * (LPAD/8);
    const int arow = t >> 1, akc = (t & 1) << 2;
    const float* Aptr = W + (size_t)(bm + arow)*LPAD + akc;
    const int brow = (t & 127) >> 1;
    const float* Bptr = Bb + (size_t)brow*LPAD + akc;

    for (int k0 = kbeg; k0 < kbeg + LPAD/8; k0 += 8) {
        float4 a4 = *(const float4*)(Aptr + k0);
        As[akc+0][arow] = a4.x; As[akc+1][arow] = a4.y;
        As[akc+2][arow] = a4.z; As[akc+3][arow] = a4.w;
        if (t < 128) {
            float4 b4 = *(const float4*)(Bptr + k0);
            Bs[akc+0][brow] = b4.x; Bs[akc+1][brow] = b4.y;
            Bs[akc+2][brow] = b4.z; Bs[akc+3][brow] = b4.w;
        }
        __syncthreads();
#pragma unroll
        for (int kk = 0; kk < 8; kk++) {
            float4 a0 = *(const float4*)&As[kk][ty << 3];
            float4 a1 = *(const float4*)&As[kk][(ty << 3) + 4];
            float4 b0 = *(const float4*)&Bs[kk][tx << 2];
            float ra[8] = {a0.x,a0.y,a0.z,a0.w,a1.x,a1.y,a1.z,a1.w};
            float rb[4] = {b0.x,b0.y,b0.z,b0.w};
#pragma unroll
            for (int i = 0; i < 8; i++)
#pragma unroll
                for (int j = 0; j < 4; j++)
                    acc[i][j] = fmaf(ra[i], rb[j], acc[i][j]);
        }
        __syncthreads();
    }
    float* pb = g_part + (size_t)(split*2 + b)*64*NQ;
#pragma unroll
    for (int j = 0; j < 4; j++) {
        int c = (tx << 2) + j;
        float4 v0 = make_float4(acc[0][j],acc[1][j],acc[2][j],acc[3][j]);
        float4 v1 = make_float4(acc[4][j],acc[5][j],acc[6][j],acc[7][j]);
        *(float4*)(pb + (size_t)c*NQ + bm + (ty << 3))     = v0;
        *(float4*)(pb + (size_t)c*NQ + bm + (ty << 3) + 4) = v1;
    }
}

// ---------------- stage 7: reduce partials + residual ----------------
__global__ void k_final(const float* __restrict__ inp, float* __restrict__ out) {
    int idx = blockIdx.x * blockDim.x + threadIdx.x;   // 2*64*4096
    if (idx >= 2*64*4096) return;
    int q = idx & 4095;
    int c = (idx >> 12) & 63;
    int b = idx >> 18;
    float s = 0.0f;
#pragma unroll
    for (int sp = 0; sp < 8; sp++)
        s += g_part[(size_t)(sp*2 + b)*64*NQ + (size_t)c*NQ + q];
    out[idx] = inp[idx] + 0.25f * s;
}

// ---------------- launch ----------------
extern "C" void kernel_launch(void* const* d_in, const int* in_sizes, int n_in,
                              void* d_out, int out_size) {
    const float* input     = (const float*)d_in[0];
    const float* input_ref = (const float*)d_in[1];
    const float* Wb  = (const float*)d_in[2];
    const float* bbv = (const float*)d_in[3];
    const float* Wm  = (const float*)d_in[4];
    const float* bmv = (const float*)d_in[5];
    const float* Wa  = (const float*)d_in[6];
    const float* bav = (const float*)d_in[7];
    const float* ap  = (const float*)d_in[8];
    float* out = (float*)d_out;

    cudaFuncSetAttribute(k_shift<true>, cudaFuncAttributeMaxDynamicSharedMemorySize, LPAD*4);

    k_matchbase  <<<1024, 256>>>(input, Wb, bbv, ap);
    k_resize_conv<<<dim3(1666, 2), 128>>>(input_ref, Wm, bmv, Wa, bav, ap);
    k_prep       <<<105, 128>>>();
    k_invnrm     <<<dim3(105, 2), 128>>>();
    k_gemm_G     <<<dim3(105, 32, 2), 256>>>();
    k_shift<true> <<<dim3(NQ, 2), 256, LPAD*4>>>();
    k_shift<false><<<dim3(NQ, 2), 256>>>();
    k_gemm_W     <<<dim3(8, 32, 2), 256>>>();
    k_final      <<<2048, 256>>>(input, out);
}